// round 4
// baseline (speedup 1.0000x reference)
#include <cuda_runtime.h>
#include <cuda_bf16.h>
#include <math.h>

// ForwardBackwardImputer: out[b,t,:] = x[b, idx_fwd[b,t], :]
// mask[t] = all(|x[b,t,d]| <= 1e-6); idx_fwd = inclusive cummax(mask ? 0 : t).
// (Backward-fill branch of the reference is provably identical to x_fwd.)

#define L_SEQ 2048
#define D_FEAT 128
#define NTHREADS 512
#define NWARPS 16
#define ROW_F4 (D_FEAT / 4)   // 32 float4 per row
#define ATOL_F 1e-6f

__global__ __launch_bounds__(NTHREADS, 2)
void fwd_fill_kernel(const float* __restrict__ x, float* __restrict__ out) {
    const int b = blockIdx.x;
    const float4* __restrict__ xb =
        reinterpret_cast<const float4*>(x + (size_t)b * L_SEQ * D_FEAT);
    float4* __restrict__ ob =
        reinterpret_cast<float4*>(out + (size_t)b * L_SEQ * D_FEAT);

    __shared__ unsigned char s_mask[L_SEQ];
    __shared__ short s_idx[L_SEQ];
    __shared__ int s_wtot[NWARPS];

    const int tid  = threadIdx.x;
    const int lane = tid & 31;
    const int wid  = tid >> 5;
    const unsigned FULL = 0xffffffffu;

    // ------------- Phase 1: mask + copy-through valid rows (x4 ILP) -------
    // Warp w owns rows [4w, 4w+4) then strides by 64. 4 independent LDG.128
    // are issued before any ballot consumes them -> MLP ~4x.
    for (int t0 = wid << 2; t0 < L_SEQ; t0 += (NWARPS << 2)) {
        float4 v0 = xb[(t0 + 0) * ROW_F4 + lane];
        float4 v1 = xb[(t0 + 1) * ROW_F4 + lane];
        float4 v2 = xb[(t0 + 2) * ROW_F4 + lane];
        float4 v3 = xb[(t0 + 3) * ROW_F4 + lane];

        bool z0 = (fabsf(v0.x) <= ATOL_F) & (fabsf(v0.y) <= ATOL_F) &
                  (fabsf(v0.z) <= ATOL_F) & (fabsf(v0.w) <= ATOL_F);
        bool z1 = (fabsf(v1.x) <= ATOL_F) & (fabsf(v1.y) <= ATOL_F) &
                  (fabsf(v1.z) <= ATOL_F) & (fabsf(v1.w) <= ATOL_F);
        bool z2 = (fabsf(v2.x) <= ATOL_F) & (fabsf(v2.y) <= ATOL_F) &
                  (fabsf(v2.z) <= ATOL_F) & (fabsf(v2.w) <= ATOL_F);
        bool z3 = (fabsf(v3.x) <= ATOL_F) & (fabsf(v3.y) <= ATOL_F) &
                  (fabsf(v3.z) <= ATOL_F) & (fabsf(v3.w) <= ATOL_F);

        unsigned m0 = __all_sync(FULL, z0);
        unsigned m1 = __all_sync(FULL, z1);
        unsigned m2 = __all_sync(FULL, z2);
        unsigned m3 = __all_sync(FULL, z3);

        if (!m0) ob[(t0 + 0) * ROW_F4 + lane] = v0;
        if (!m1) ob[(t0 + 1) * ROW_F4 + lane] = v1;
        if (!m2) ob[(t0 + 2) * ROW_F4 + lane] = v2;
        if (!m3) ob[(t0 + 3) * ROW_F4 + lane] = v3;

        if (lane == 0) {
            uchar4 mm = make_uchar4((unsigned char)m0, (unsigned char)m1,
                                    (unsigned char)m2, (unsigned char)m3);
            *reinterpret_cast<uchar4*>(&s_mask[t0]) = mm;
        }
    }
    __syncthreads();

    // ------------- Phase 2: block-wide inclusive max-scan ------------------
    const int t0 = tid << 2;
    int vloc[4];
    int run = 0;
    #pragma unroll
    for (int i = 0; i < 4; i++) {
        int t = t0 + i;
        int v = s_mask[t] ? 0 : t;
        if (v > run) run = v;
        vloc[i] = run;
    }

    int incl = run;
    #pragma unroll
    for (int o = 1; o < 32; o <<= 1) {
        int n = __shfl_up_sync(FULL, incl, o);
        if (lane >= o && n > incl) incl = n;
    }
    if (lane == 31) s_wtot[wid] = incl;
    int pre = __shfl_up_sync(FULL, incl, 1);
    int texcl = (lane == 0) ? 0 : pre;
    __syncthreads();

    if (tid == 0) {
        int r = 0;
        #pragma unroll
        for (int w = 0; w < NWARPS; w++) {
            int tmp = s_wtot[w];
            s_wtot[w] = r;
            if (tmp > r) r = tmp;
        }
    }
    __syncthreads();

    int base = s_wtot[wid];
    if (texcl > base) base = texcl;
    #pragma unroll
    for (int i = 0; i < 4; i++) {
        int v = vloc[i] > base ? vloc[i] : base;
        s_idx[t0 + i] = (short)v;
    }
    __syncthreads();

    // ------------- Phase 3: fill masked rows via gather (x4 structure) -----
    for (int tt = wid << 2; tt < L_SEQ; tt += (NWARPS << 2)) {
        uchar4 mm = *reinterpret_cast<const uchar4*>(&s_mask[tt]);
        if (mm.x) ob[(tt + 0) * ROW_F4 + lane] = xb[(int)s_idx[tt + 0] * ROW_F4 + lane];
        if (mm.y) ob[(tt + 1) * ROW_F4 + lane] = xb[(int)s_idx[tt + 1] * ROW_F4 + lane];
        if (mm.z) ob[(tt + 2) * ROW_F4 + lane] = xb[(int)s_idx[tt + 2] * ROW_F4 + lane];
        if (mm.w) ob[(tt + 3) * ROW_F4 + lane] = xb[(int)s_idx[tt + 3] * ROW_F4 + lane];
    }
}

extern "C" void kernel_launch(void* const* d_in, const int* in_sizes, int n_in,
                              void* d_out, int out_size) {
    const float* x = (const float*)d_in[0];
    float* out = (float*)d_out;
    int B = in_sizes[0] / (L_SEQ * D_FEAT);
    fwd_fill_kernel<<<B, NTHREADS>>>(x, out);
}